// round 1
// baseline (speedup 1.0000x reference)
#include <cuda_runtime.h>
#include <cstdint>
#include <math.h>

// Problem constants
#define Dk 128
#define Bk 1024
#define Rk 131072
#define NN 10
#define BN (Bk * NN)      // 10240 gathered neighbors
#define CHUNK 512
#define NCH (Rk / CHUNK)  // 256 chunks
#define CT 64             // cols per smem tile
#define RTt 64            // rows per smem tile
#define NRT (Bk / RTt)    // 16 row tiles
#define SPITCH (CT + 1)
#define JC 8              // j-chunks in stage 2
#define JCH (BN / JC)     // 1280

typedef unsigned long long u64;

// ---------------- device scratch (static: no allocations allowed) -------------
__device__ float g_feat[2][Bk * Dk];          // normalized features
__device__ float g_candV[Bk * NCH * NN];      // top-k candidates per (row, chunk)
__device__ int   g_candI[Bk * NCH * NN];
__device__ int   g_topk[2][Bk * NN];          // final top-10 indices
__device__ float g_nnT[Dk * BN];              // gathered neighbor features, [d][j]
__device__ float g_pM[2][Bk][JC];             // partial LSE max
__device__ float g_pS[2][Bk][JC];             // partial LSE sum
__device__ float g_pP[2][Bk][JC];             // partial positive-logit sum

// ---------------- f32x2 helpers -----------------------------------------------
__device__ __forceinline__ void ffma2(u64 &d, u64 a, u64 b) {
    asm("fma.rn.f32x2 %0, %1, %2, %0;" : "+l"(d) : "l"(a), "l"(b));
}
__device__ __forceinline__ u64 dupf(float f) {
    u64 r; unsigned u = __float_as_uint(f);
    asm("mov.b64 %0, {%1, %2};" : "=l"(r) : "r"(u), "r"(u));
    return r;
}
__device__ __forceinline__ float2 unpack2(u64 a) {
    float2 o;
    asm("mov.b64 {%0, %1}, %2;" : "=f"(o.x), "=f"(o.y) : "l"(a));
    return o;
}

// ---------------- 1. normalize rows --------------------------------------------
__global__ void normalize_kernel(const float* __restrict__ fX,
                                 const float* __restrict__ fY) {
    int side = blockIdx.y;
    int row = blockIdx.x;
    int d = threadIdx.x;
    const float* in = side ? fY : fX;
    float v = in[row * Dk + d];
    float sq = v * v;
    #pragma unroll
    for (int o = 16; o; o >>= 1) sq += __shfl_xor_sync(0xFFFFFFFFu, sq, o);
    __shared__ float ws[4];
    __shared__ float nrm;
    if ((d & 31) == 0) ws[d >> 5] = sq;
    __syncthreads();
    if (d == 0) nrm = sqrtf(ws[0] + ws[1] + ws[2] + ws[3]);
    __syncthreads();
    g_feat[side][row * Dk + d] = v / nrm;
}

// ---------------- 2. fused sim GEMM + per-chunk top-10 -------------------------
// grid: NCH blocks (one per 512-column chunk), 256 threads.
// smem: Fs[64 rows][128 d] | Qs[128 d][64 c] | Ss[64][65] | TopV/TopI[64][10]
#define SMEM_FLOATS (RTt * Dk + Dk * CT + RTt * SPITCH + RTt * NN + RTt * NN)
#define SMEM_BYTES (SMEM_FLOATS * 4)

__global__ void __launch_bounds__(256, 2) simtopk_kernel(int side, const float* __restrict__ Q) {
    extern __shared__ float sm[];
    float* Fs = sm;                       // [r][d] pitch 128
    float* Qs = Fs + RTt * Dk;            // [d][c] pitch 64
    float* Ss = Qs + Dk * CT;             // [r][c] pitch 65
    float* Tv = Ss + RTt * SPITCH;        // [r][10]
    int*   Ti = reinterpret_cast<int*>(Tv + RTt * NN);

    int t = threadIdx.x;
    int tx = t & 15, ty = t >> 4;
    int chunk = blockIdx.x;
    int colBase = chunk * CHUNK;
    const float* feat = g_feat[side];
    const float4* Qg = reinterpret_cast<const float4*>(Q);

    for (int rt = 0; rt < NRT; ++rt) {
        // load 64 feature rows (contiguous copy)
        const float4* fg = reinterpret_cast<const float4*>(feat + rt * RTt * Dk);
        float4* Fs4 = reinterpret_cast<float4*>(Fs);
        #pragma unroll
        for (int i = 0; i < 8; ++i) Fs4[i * 256 + t] = fg[i * 256 + t];
        for (int i = t; i < RTt * NN; i += 256) { Tv[i] = -1e30f; Ti[i] = 0; }
        __syncthreads();

        for (int ct = 0; ct < CHUNK / CT; ++ct) {
            // load Q tile [128 d][64 c]
            int cb4 = (colBase + ct * CT) >> 2;
            float4* Qs4 = reinterpret_cast<float4*>(Qs);
            #pragma unroll
            for (int i = 0; i < 8; ++i) {
                int lin = i * 256 + t;
                int d = lin >> 4, c4 = lin & 15;
                Qs4[d * 16 + c4] = Qg[d * (Rk >> 2) + cb4 + c4];
            }
            __syncthreads();

            // 4 rows x 4 cols per thread, cols packed in f32x2 pairs
            u64 acc[4][2];
            #pragma unroll
            for (int r = 0; r < 4; ++r) { acc[r][0] = 0ull; acc[r][1] = 0ull; }
            const float* fb = Fs + (ty * 4) * Dk;
            #pragma unroll 8
            for (int d = 0; d < Dk; ++d) {
                ulonglong2 q = *reinterpret_cast<const ulonglong2*>(Qs + d * CT + tx * 4);
                #pragma unroll
                for (int r = 0; r < 4; ++r) {
                    u64 fd = dupf(fb[r * Dk + d]);
                    ffma2(acc[r][0], q.x, fd);
                    ffma2(acc[r][1], q.y, fd);
                }
            }

            // write sims to smem
            #pragma unroll
            for (int r = 0; r < 4; ++r) {
                float2 a = unpack2(acc[r][0]);
                float2 b2 = unpack2(acc[r][1]);
                float* sp = Ss + (ty * 4 + r) * SPITCH + tx * 4;
                sp[0] = a.x; sp[1] = a.y; sp[2] = b2.x; sp[3] = b2.y;
            }
            __syncthreads();

            // per-row top-10 update (one thread per row)
            if (t < RTt) {
                float* tv = Tv + t * NN;
                int*   ti = Ti + t * NN;
                const float* sp = Ss + t * SPITCH;
                int base = colBase + ct * CT;
                for (int c = 0; c < CT; ++c) {
                    float vv = sp[c];
                    if (vv > tv[NN - 1]) {
                        int p = NN - 1;
                        while (p > 0 && tv[p - 1] < vv) {
                            tv[p] = tv[p - 1]; ti[p] = ti[p - 1]; --p;
                        }
                        tv[p] = vv; ti[p] = base + c;
                    }
                }
            }
            __syncthreads();
        }

        // write candidates: layout [row][chunk][k] so phase B reads contiguously
        for (int i = t; i < RTt * NN; i += 256) {
            int row = i / NN, k = i % NN;
            int gRow = rt * RTt + row;
            g_candV[(gRow * NCH + chunk) * NN + k] = Tv[i];
            g_candI[(gRow * NCH + chunk) * NN + k] = Ti[i];
        }
        __syncthreads();
    }
}

// ---------------- 3. reduce 2560 candidates -> top-10 per row ------------------
__global__ void topk_reduce_kernel(int side) {
    __shared__ float v[NCH * NN];
    __shared__ int   id[NCH * NN];
    __shared__ float bv[256];
    __shared__ int   bp[256];
    int row = blockIdx.x;
    int t = threadIdx.x;
    for (int i = t; i < NCH * NN; i += 256) {
        v[i] = g_candV[row * (NCH * NN) + i];
        id[i] = g_candI[row * (NCH * NN) + i];
    }
    __syncthreads();
    for (int k = 0; k < NN; ++k) {
        float best = -1e38f; int bpos = -1;
        for (int i = t; i < NCH * NN; i += 256) {
            float x = v[i];
            if (bpos < 0 || x > best || (x == best && id[i] < id[bpos])) { best = x; bpos = i; }
        }
        bv[t] = best; bp[t] = bpos;
        __syncthreads();
        for (int s = 128; s; s >>= 1) {
            if (t < s) {
                float xb = bv[t + s]; int xp = bp[t + s];
                bool take = (xp >= 0) && (bp[t] < 0 || xb > bv[t] ||
                             (xb == bv[t] && id[xp] < id[bp[t]]));
                if (take) { bv[t] = xb; bp[t] = xp; }
            }
            __syncthreads();
        }
        if (t == 0) { g_topk[side][row * NN + k] = id[bp[0]]; v[bp[0]] = -1e38f; }
        __syncthreads();
    }
}

// ---------------- 4. gather neighbor columns into dense [d][j] -----------------
__global__ void gather_kernel(int side, const float* __restrict__ Q) {
    int j = blockIdx.x * 256 + threadIdx.x;   // < BN
    int d = blockIdx.y;
    int c = g_topk[side][j];
    g_nnT[d * BN + j] = Q[(size_t)d * Rk + c];
}

// ---------------- 5. stage-2 logits + partial logsumexp ------------------------
// grid (Bk/16 row-groups, JC j-chunks), 256 threads: 16 rows x 16 lanes.
__global__ void lse_partial_kernel(int side) {
    __shared__ float Ff[16 * Dk];
    __shared__ float rm[256], rs[256], rp[256];
    int t = threadIdx.x;
    int rg = blockIdx.x;
    int jc = blockIdx.y;
    const float* feat = g_feat[side];
    for (int i = t; i < 16 * Dk; i += 256) Ff[i] = feat[rg * 16 * Dk + i];
    __syncthreads();
    int r = t >> 4, l = t & 15;
    int row = rg * 16 + r;
    const float* frow = Ff + r * Dk;
    const float4* nn4 = reinterpret_cast<const float4*>(g_nnT);
    float m = -1e30f, s = 0.f, pos = 0.f;
    int posLo = row * NN, posHi = posLo + NN;
    for (int pass = 0; pass < JCH / 64; ++pass) {   // 20 passes
        int j4 = jc * (JCH / 4) + pass * 16 + l;
        float ax = 0.f, ay = 0.f, az = 0.f, aw = 0.f;
        #pragma unroll 8
        for (int d = 0; d < Dk; ++d) {
            float4 qv = nn4[d * (BN / 4) + j4];
            float f = frow[d];
            ax += f * qv.x; ay += f * qv.y; az += f * qv.z; aw += f * qv.w;
        }
        float vv[4] = { ax, ay, az, aw };
        int j0 = j4 * 4;
        #pragma unroll
        for (int i2 = 0; i2 < 4; ++i2) {
            float vsc = vv[i2] / 0.1f;
            if (vsc > m) { s = s * expf(m - vsc) + 1.f; m = vsc; }
            else s += expf(vsc - m);
            int j = j0 + i2;
            if (j >= posLo && j < posHi) pos += vsc;
        }
    }
    rm[t] = m; rs[t] = s; rp[t] = pos;
    __syncthreads();
    if (l == 0) {
        float M = -1e30f;
        for (int i = 0; i < 16; ++i) M = fmaxf(M, rm[r * 16 + i]);
        float S = 0.f, P = 0.f;
        for (int i = 0; i < 16; ++i) {
            S += rs[r * 16 + i] * expf(rm[r * 16 + i] - M);
            P += rp[r * 16 + i];
        }
        g_pM[side][row][jc] = M;
        g_pS[side][row][jc] = S;
        g_pP[side][row][jc] = P;
    }
}

// ---------------- 6. combine partials -> loss ----------------------------------
__global__ void combine_kernel(float* __restrict__ out) {
    __shared__ float red[1024];
    int t = threadIdx.x;   // = row
    float term = 0.f;
    #pragma unroll
    for (int side = 0; side < 2; ++side) {
        float M = -1e30f;
        for (int jcc = 0; jcc < JC; ++jcc) M = fmaxf(M, g_pM[side][t][jcc]);
        float S = 0.f, P = 0.f;
        for (int jcc = 0; jcc < JC; ++jcc) {
            S += g_pS[side][t][jcc] * expf(g_pM[side][t][jcc] - M);
            P += g_pP[side][t][jcc];
        }
        term += P - (float)NN * (M + logf(S));
    }
    red[t] = term;
    __syncthreads();
    for (int s = 512; s; s >>= 1) {
        if (t < s) red[t] += red[t + s];
        __syncthreads();
    }
    if (t == 0) out[0] = -red[0] / (float)Bk;
}

// ---------------- 7. overwrite queue head columns with normalized feats --------
__global__ void qhead_kernel(float* __restrict__ out) {
    int c = blockIdx.x * 256 + threadIdx.x;  // < Bk
    int d = blockIdx.y;
    int side = blockIdx.z;
    out[1 + (size_t)side * Dk * Rk + (size_t)d * Rk + c] = g_feat[side][c * Dk + d];
}

// ---------------- launch --------------------------------------------------------
extern "C" void kernel_launch(void* const* d_in, const int* in_sizes, int n_in,
                              void* d_out, int out_size) {
    const float* fX = (const float*)d_in[0];
    const float* fY = (const float*)d_in[1];
    const float* qX = (const float*)d_in[2];
    const float* qY = (const float*)d_in[3];
    float* out = (float*)d_out;

    cudaFuncSetAttribute(simtopk_kernel,
                         cudaFuncAttributeMaxDynamicSharedMemorySize, SMEM_BYTES);

    normalize_kernel<<<dim3(Bk, 2, 1), Dk>>>(fX, fY);

    for (int side = 0; side < 2; ++side) {
        const float* Qother = (side == 0) ? qY : qX;
        simtopk_kernel<<<NCH, 256, SMEM_BYTES>>>(side, Qother);
        topk_reduce_kernel<<<Bk, 256>>>(side);
        gather_kernel<<<dim3(BN / 256, Dk, 1), 256>>>(side, Qother);
        lse_partial_kernel<<<dim3(Bk / 16, JC, 1), 256>>>(side);
    }
    combine_kernel<<<1, 1024>>>(out);

    cudaMemcpyAsync(out + 1, qX, (size_t)Dk * Rk * sizeof(float),
                    cudaMemcpyDeviceToDevice, 0);
    cudaMemcpyAsync(out + 1 + (size_t)Dk * Rk, qY, (size_t)Dk * Rk * sizeof(float),
                    cudaMemcpyDeviceToDevice, 0);
    qhead_kernel<<<dim3(Bk / 256, Dk, 2), 256>>>(out);
}